// round 11
// baseline (speedup 1.0000x reference)
#include <cuda_runtime.h>

// 2-layer LSTM (H=8, IN=2) + FC(8->1), T=1024, B=16384.
// Warp-specialized layer pipeline: each 64-thread block owns 16 batch elems;
// warp 0 computes layer 0, warp 1 computes layer 1 one timestep behind,
// h0 handed through a 2-slot smem ring (one __syncthreads per step).
// Within a warp: 8 lanes per element, 4 elements per thread, fma.rn.f32x2
// k-packed matvecs, tanh.approx activations w/ half-prescaled sigmoid gates.

using u64 = unsigned long long;

__device__ __forceinline__ u64 pack2(float lo, float hi) {
    u64 r; asm("mov.b64 %0, {%1, %2};" : "=l"(r) : "f"(lo), "f"(hi)); return r;
}
__device__ __forceinline__ float2 unpack2(u64 v) {
    float2 f; asm("mov.b64 {%0, %1}, %2;" : "=f"(f.x), "=f"(f.y) : "l"(v)); return f;
}
__device__ __forceinline__ u64 ffma2(u64 a, u64 b, u64 c) {
    u64 d; asm("fma.rn.f32x2 %0, %1, %2, %3;" : "=l"(d) : "l"(a), "l"(b), "l"(c)); return d;
}
__device__ __forceinline__ float tanh_a(float x) {
    float y; asm("tanh.approx.f32 %0, %1;" : "=f"(y) : "f"(x)); return y;
}

__global__ void __launch_bounds__(64, 7)
lstm2_fc_kernel(const float* __restrict__ x,
                const float* __restrict__ w_ih0, const float* __restrict__ w_hh0,
                const float* __restrict__ b_ih0, const float* __restrict__ b_hh0,
                const float* __restrict__ w_ih1, const float* __restrict__ w_hh1,
                const float* __restrict__ b_ih1, const float* __restrict__ b_hh1,
                const float* __restrict__ fc_w, const float* __restrict__ fc_b,
                float* __restrict__ out, int T, int B)
{
    // 2-slot h0 pipeline ring + warp1's private h1 broadcast buffer.
    __shared__ alignas(16) float pipe[2][4][4][8];  // [slot][p][ql][j]
    __shared__ alignas(16) float h1s[4][4][8];

    int lane = threadIdx.x & 31;
    int wid  = threadIdx.x >> 5;   // 0 = layer0 warp, 1 = layer1 warp
    int ql   = lane >> 3;          // quad slot within warp (0..3)
    int j    = lane & 7;           // hidden unit owned by this lane
    int q    = blockIdx.x * 4 + ql;        // global quad: elements 4q..4q+3
    int quadB = B >> 2;
    if (q >= quadB) q = quadB - 1;

    u64 zero2 = pack2(0.0f, 0.0f);

    if (wid == 0) {
        // ================= Layer-0 warp =================
        u64 wi0p[4], wh0p[4][4], zb0p[4];
#pragma unroll
        for (int g = 0; g < 4; g++) {
            float sc = (g == 2) ? 1.0f : 0.5f;
            int r = g * 8 + j;
            wi0p[g] = pack2(sc * __ldg(&w_ih0[r * 2 + 0]), sc * __ldg(&w_ih0[r * 2 + 1]));
#pragma unroll
            for (int m = 0; m < 4; m++)
                wh0p[g][m] = pack2(sc * __ldg(&w_hh0[r * 8 + 2 * m]),
                                   sc * __ldg(&w_hh0[r * 8 + 2 * m + 1]));
            zb0p[g] = pack2(sc * (__ldg(&b_ih0[r]) + __ldg(&b_hh0[r])), 0.0f);
        }

        u64 h0p[4][4];
        float c0[4];
#pragma unroll
        for (int p = 0; p < 4; p++) {
            c0[p] = 0.0f;
#pragma unroll
            for (int m = 0; m < 4; m++) h0p[p][m] = zero2;
        }

        int strideT = B >> 1;
        const ulonglong2* xp = (const ulonglong2*)x + 2 * q;
        ulonglong2 xa = __ldg(xp);
        ulonglong2 xb = __ldg(xp + 1);

#pragma unroll 1
        for (int t = 0; t < T; t++) {
            const ulonglong2* xn = xp + ((t + 1 < T) ? strideT : 0);
            ulonglong2 na = __ldg(xn);
            ulonglong2 nb = __ldg(xn + 1);
            u64 xq[4] = { xa.x, xa.y, xb.x, xb.y };
            int s = t & 1;

#pragma unroll
            for (int p = 0; p < 4; p++) {
                float z[4];
#pragma unroll
                for (int g = 0; g < 4; g++) {
                    u64 acc = ffma2(wi0p[g], xq[p], zb0p[g]);
#pragma unroll
                    for (int m = 0; m < 4; m++)
                        acc = ffma2(wh0p[g][m], h0p[p][m], acc);
                    float2 u = unpack2(acc);
                    z[g] = u.x + u.y;
                }
                float ig = fmaf(tanh_a(z[0]), 0.5f, 0.5f);
                float fg = fmaf(tanh_a(z[1]), 0.5f, 0.5f);
                float gg = tanh_a(z[2]);
                float og = fmaf(tanh_a(z[3]), 0.5f, 0.5f);
                c0[p] = fmaf(fg, c0[p], ig * gg);
                pipe[s][p][ql][j] = og * tanh_a(c0[p]);
            }
            __syncwarp();
            // Read back own h0 (packed) for the recurrence.
#pragma unroll
            for (int p = 0; p < 4; p++) {
                const ulonglong2* row = (const ulonglong2*)&pipe[s][p][ql][0];
                ulonglong2 va = row[0], vb = row[1];
                h0p[p][0] = va.x; h0p[p][1] = va.y;
                h0p[p][2] = vb.x; h0p[p][3] = vb.y;
            }
            xa = na; xb = nb; xp = xn;
            __syncthreads();
        }
    } else {
        // ================= Layer-1 warp =================
        u64 wi1p[4][4], wh1p[4][4], zb1p[4];
#pragma unroll
        for (int g = 0; g < 4; g++) {
            float sc = (g == 2) ? 1.0f : 0.5f;
            int r = g * 8 + j;
#pragma unroll
            for (int m = 0; m < 4; m++) {
                wi1p[g][m] = pack2(sc * __ldg(&w_ih1[r * 8 + 2 * m]),
                                   sc * __ldg(&w_ih1[r * 8 + 2 * m + 1]));
                wh1p[g][m] = pack2(sc * __ldg(&w_hh1[r * 8 + 2 * m]),
                                   sc * __ldg(&w_hh1[r * 8 + 2 * m + 1]));
            }
            zb1p[g] = pack2(sc * (__ldg(&b_ih1[r]) + __ldg(&b_hh1[r])), 0.0f);
        }

        u64 h1p[4][4];
        float c1[4];
#pragma unroll
        for (int p = 0; p < 4; p++) {
            c1[p] = 0.0f;
#pragma unroll
            for (int m = 0; m < 4; m++) h1p[p][m] = zero2;
        }

        // Iter i consumes h0(i-1) from slot (i-1)&1 (skip i==0); after the
        // loop, one epilogue step consumes h0(T-1).
#pragma unroll 1
        for (int i = 0; i < T; i++) {
            if (i > 0) {
                int s = (i - 1) & 1;
#pragma unroll
                for (int p = 0; p < 4; p++) {
                    const ulonglong2* row = (const ulonglong2*)&pipe[s][p][ql][0];
                    ulonglong2 va = row[0], vb = row[1];
                    u64 h0v[4] = { va.x, va.y, vb.x, vb.y };

                    float z[4];
#pragma unroll
                    for (int g = 0; g < 4; g++) {
                        u64 acc = ffma2(wi1p[g][0], h0v[0], zb1p[g]);
#pragma unroll
                        for (int m = 1; m < 4; m++)
                            acc = ffma2(wi1p[g][m], h0v[m], acc);
#pragma unroll
                        for (int m = 0; m < 4; m++)
                            acc = ffma2(wh1p[g][m], h1p[p][m], acc);
                        float2 u = unpack2(acc);
                        z[g] = u.x + u.y;
                    }
                    float ig = fmaf(tanh_a(z[0]), 0.5f, 0.5f);
                    float fg = fmaf(tanh_a(z[1]), 0.5f, 0.5f);
                    float gg = tanh_a(z[2]);
                    float og = fmaf(tanh_a(z[3]), 0.5f, 0.5f);
                    c1[p] = fmaf(fg, c1[p], ig * gg);
                    h1s[p][ql][j] = og * tanh_a(c1[p]);
                }
                __syncwarp();
#pragma unroll
                for (int p = 0; p < 4; p++) {
                    const ulonglong2* row = (const ulonglong2*)&h1s[p][ql][0];
                    ulonglong2 va = row[0], vb = row[1];
                    h1p[p][0] = va.x; h1p[p][1] = va.y;
                    h1p[p][2] = vb.x; h1p[p][3] = vb.y;
                }
            }
            __syncthreads();
        }

        // ---- Epilogue: layer-1 step for t = T-1 ----
        {
            int s = (T - 1) & 1;
            float h1fin[4];     // own j-component of final h1 per element
#pragma unroll
            for (int p = 0; p < 4; p++) {
                const ulonglong2* row = (const ulonglong2*)&pipe[s][p][ql][0];
                ulonglong2 va = row[0], vb = row[1];
                u64 h0v[4] = { va.x, va.y, vb.x, vb.y };

                float z[4];
#pragma unroll
                for (int g = 0; g < 4; g++) {
                    u64 acc = ffma2(wi1p[g][0], h0v[0], zb1p[g]);
#pragma unroll
                    for (int m = 1; m < 4; m++)
                        acc = ffma2(wi1p[g][m], h0v[m], acc);
#pragma unroll
                    for (int m = 0; m < 4; m++)
                        acc = ffma2(wh1p[g][m], h1p[p][m], acc);
                    float2 u = unpack2(acc);
                    z[g] = u.x + u.y;
                }
                float ig = fmaf(tanh_a(z[0]), 0.5f, 0.5f);
                float fg = fmaf(tanh_a(z[1]), 0.5f, 0.5f);
                float gg = tanh_a(z[2]);
                float og = fmaf(tanh_a(z[3]), 0.5f, 0.5f);
                c1[p] = fmaf(fg, c1[p], ig * gg);
                h1fin[p] = og * tanh_a(c1[p]);
            }

            // FC: out[b] = sum_j fc_w[j] * h1[j] + fc_b, reduce across lanes.
            float fwj = __ldg(&fc_w[j]);
            float fb  = __ldg(&fc_b[0]);
            float4 o;
            float* op = &o.x;
#pragma unroll
            for (int p = 0; p < 4; p++) {
                float v = fwj * h1fin[p];
#pragma unroll
                for (int d = 4; d >= 1; d >>= 1)
                    v += __shfl_down_sync(0xffffffffu, v, d, 8);
                op[p] = v + fb;
            }
            if (j == 0 && q < quadB)
                *(float4*)&out[4 * q] = o;
        }
    }
}

extern "C" void kernel_launch(void* const* d_in, const int* in_sizes, int n_in,
                              void* d_out, int out_size)
{
    const float* x      = (const float*)d_in[0];
    const float* w_ih0  = (const float*)d_in[1];
    const float* w_hh0  = (const float*)d_in[2];
    const float* b_ih0  = (const float*)d_in[3];
    const float* b_hh0  = (const float*)d_in[4];
    const float* w_ih1  = (const float*)d_in[5];
    const float* w_hh1  = (const float*)d_in[6];
    const float* b_ih1  = (const float*)d_in[7];
    const float* b_hh1  = (const float*)d_in[8];
    const float* fc_w   = (const float*)d_in[9];
    const float* fc_b   = (const float*)d_in[10];
    float* out = (float*)d_out;

    int B = out_size;                 // [B, 1]
    int T = in_sizes[0] / (2 * B);    // x: [T, B, 2]

    int blocks = (B + 15) / 16;       // 16 elements per block (4 per thread)
    lstm2_fc_kernel<<<blocks, 64>>>(x, w_ih0, w_hh0, b_ih0, b_hh0,
                                    w_ih1, w_hh1, b_ih1, b_hh1,
                                    fc_w, fc_b, out, T, B);
}

// round 12
// speedup vs baseline: 1.3815x; 1.3815x over previous
#include <cuda_runtime.h>

// 2-layer LSTM (H=8, IN=2) + FC(8->1), T=1024, B=16384.
// E=4 elems/thread, 8 lanes/elem, 1024 single-warp blocks (one wave).
// WITHIN-THREAD layer pipeline: iteration i computes h0(i) AND h1(i-1),
// both reading only last iteration's broadcast state -> 32 independent
// FFMA2 chains per phase and ONE smem broadcast (STS/syncwarp/LDS) per step.
// fma.rn.f32x2 k-packed matvecs, tanh.approx activations, half-prescaled
// sigmoid-gate weights.

using u64 = unsigned long long;

__device__ __forceinline__ u64 pack2(float lo, float hi) {
    u64 r; asm("mov.b64 %0, {%1, %2};" : "=l"(r) : "f"(lo), "f"(hi)); return r;
}
__device__ __forceinline__ float2 unpack2(u64 v) {
    float2 f; asm("mov.b64 {%0, %1}, %2;" : "=f"(f.x), "=f"(f.y) : "l"(v)); return f;
}
__device__ __forceinline__ u64 ffma2(u64 a, u64 b, u64 c) {
    u64 d; asm("fma.rn.f32x2 %0, %1, %2, %3;" : "=l"(d) : "l"(a), "l"(b), "l"(c)); return d;
}
__device__ __forceinline__ float tanh_a(float x) {
    float y; asm("tanh.approx.f32 %0, %1;" : "=f"(y) : "f"(x)); return y;
}

__global__ void __launch_bounds__(32)
lstm2_fc_kernel(const float* __restrict__ x,
                const float* __restrict__ w_ih0, const float* __restrict__ w_hh0,
                const float* __restrict__ b_ih0, const float* __restrict__ b_hh0,
                const float* __restrict__ w_ih1, const float* __restrict__ w_hh1,
                const float* __restrict__ b_ih1, const float* __restrict__ b_hh1,
                const float* __restrict__ fc_w, const float* __restrict__ fc_b,
                float* __restrict__ out, int T, int B)
{
    // Double-buffered broadcast: [slot][elem p][quad ql][hidden j].
    __shared__ alignas(16) float h0s[2][4][4][8];
    __shared__ alignas(16) float h1s[2][4][4][8];

    int lane  = threadIdx.x;
    int ql    = lane >> 3;         // quad slot within warp (0..3)
    int j     = lane & 7;          // hidden unit owned by this lane
    int q     = blockIdx.x * 4 + ql;   // global quad: elements 4q..4q+3
    int quadB = B >> 2;
    bool valid = (q < quadB);
    if (!valid) q = quadB - 1;

    // ---- Per-lane weights; sigmoid-gate rows (i,f,o) prescaled by 0.5 ----
    u64 wi0p[4], wh0p[4][4], wi1p[4][4], wh1p[4][4], zb0p[4], zb1p[4];
#pragma unroll
    for (int g = 0; g < 4; g++) {
        float sc = (g == 2) ? 1.0f : 0.5f;
        int r = g * 8 + j;
        wi0p[g] = pack2(sc * __ldg(&w_ih0[r * 2 + 0]), sc * __ldg(&w_ih0[r * 2 + 1]));
#pragma unroll
        for (int m = 0; m < 4; m++) {
            wh0p[g][m] = pack2(sc * __ldg(&w_hh0[r * 8 + 2 * m]), sc * __ldg(&w_hh0[r * 8 + 2 * m + 1]));
            wi1p[g][m] = pack2(sc * __ldg(&w_ih1[r * 8 + 2 * m]), sc * __ldg(&w_ih1[r * 8 + 2 * m + 1]));
            wh1p[g][m] = pack2(sc * __ldg(&w_hh1[r * 8 + 2 * m]), sc * __ldg(&w_hh1[r * 8 + 2 * m + 1]));
        }
        zb0p[g] = pack2(sc * (__ldg(&b_ih0[r]) + __ldg(&b_hh0[r])), 0.0f);
        zb1p[g] = pack2(sc * (__ldg(&b_ih1[r]) + __ldg(&b_hh1[r])), 0.0f);
    }

    // ---- State: h0p = h0(i-1) replicated, h1p = h1(i-2) replicated ----
    u64 h0p[4][4], h1p[4][4];
    float c0[4], c1[4];
    u64 zero2 = pack2(0.0f, 0.0f);
#pragma unroll
    for (int p = 0; p < 4; p++) {
        c0[p] = 0.0f; c1[p] = 0.0f;
#pragma unroll
        for (int m = 0; m < 4; m++) { h0p[p][m] = zero2; h1p[p][m] = zero2; }
    }

    int strideT = B >> 1;                       // ulonglong2 per timestep row
    const ulonglong2* xp = (const ulonglong2*)x + 2 * q;
    ulonglong2 xa = __ldg(xp);                  // x(0)
    ulonglong2 xb = __ldg(xp + 1);

    // ================= Prologue: h0(0) = L0(x(0), 0) =================
    {
        u64 xq[4] = { xa.x, xa.y, xb.x, xb.y };
#pragma unroll
        for (int p = 0; p < 4; p++) {
            float z[4];
#pragma unroll
            for (int g = 0; g < 4; g++) {
                u64 acc = ffma2(wi0p[g], xq[p], zb0p[g]);   // h0(-1)=0
                float2 u = unpack2(acc);
                z[g] = u.x + u.y;
            }
            float ig = fmaf(tanh_a(z[0]), 0.5f, 0.5f);
            float fg = fmaf(tanh_a(z[1]), 0.5f, 0.5f);
            float gg = tanh_a(z[2]);
            float og = fmaf(tanh_a(z[3]), 0.5f, 0.5f);
            c0[p] = fmaf(fg, c0[p], ig * gg);
            h0s[0][p][ql][j] = og * tanh_a(c0[p]);
        }
        __syncwarp();
#pragma unroll
        for (int p = 0; p < 4; p++) {
            const ulonglong2* row = (const ulonglong2*)&h0s[0][p][ql][0];
            ulonglong2 va = row[0], vb = row[1];
            h0p[p][0] = va.x; h0p[p][1] = va.y;
            h0p[p][2] = vb.x; h0p[p][3] = vb.y;
        }
        // advance x to x(1)
        xp += strideT;
        xa = __ldg(xp);
        xb = __ldg(xp + 1);
    }

    // ============ Main loop: i = 1..T-1 computes h0(i) & h1(i-1) ============
#pragma unroll 1
    for (int i = 1; i < T; i++) {
        const ulonglong2* xn = xp + ((i + 1 < T) ? strideT : 0);
        ulonglong2 na = __ldg(xn);
        ulonglong2 nb = __ldg(xn + 1);
        u64 xq[4] = { xa.x, xa.y, xb.x, xb.y };
        int s = i & 1;

#pragma unroll
        for (int p = 0; p < 4; p++) {
            // ---- L0(i): z0 from x(i), h0(i-1) ----
            float z0[4];
#pragma unroll
            for (int g = 0; g < 4; g++) {
                u64 acc = ffma2(wi0p[g], xq[p], zb0p[g]);
#pragma unroll
                for (int m = 0; m < 4; m++)
                    acc = ffma2(wh0p[g][m], h0p[p][m], acc);
                float2 u = unpack2(acc);
                z0[g] = u.x + u.y;
            }
            // ---- L1(i-1): z1 from h0(i-1), h1(i-2) ----
            float z1[4];
#pragma unroll
            for (int g = 0; g < 4; g++) {
                u64 acc = ffma2(wi1p[g][0], h0p[p][0], zb1p[g]);
#pragma unroll
                for (int m = 1; m < 4; m++)
                    acc = ffma2(wi1p[g][m], h0p[p][m], acc);
#pragma unroll
                for (int m = 0; m < 4; m++)
                    acc = ffma2(wh1p[g][m], h1p[p][m], acc);
                float2 u = unpack2(acc);
                z1[g] = u.x + u.y;
            }
            // ---- activations (both layers batched) ----
            float i0 = fmaf(tanh_a(z0[0]), 0.5f, 0.5f);
            float f0 = fmaf(tanh_a(z0[1]), 0.5f, 0.5f);
            float g0 = tanh_a(z0[2]);
            float o0 = fmaf(tanh_a(z0[3]), 0.5f, 0.5f);
            float i1 = fmaf(tanh_a(z1[0]), 0.5f, 0.5f);
            float f1 = fmaf(tanh_a(z1[1]), 0.5f, 0.5f);
            float g1 = tanh_a(z1[2]);
            float o1 = fmaf(tanh_a(z1[3]), 0.5f, 0.5f);
            c0[p] = fmaf(f0, c0[p], i0 * g0);
            c1[p] = fmaf(f1, c1[p], i1 * g1);
            h0s[s][p][ql][j] = o0 * tanh_a(c0[p]);
            h1s[s][p][ql][j] = o1 * tanh_a(c1[p]);
        }
        __syncwarp();
#pragma unroll
        for (int p = 0; p < 4; p++) {
            const ulonglong2* r0 = (const ulonglong2*)&h0s[s][p][ql][0];
            ulonglong2 a0 = r0[0], b0 = r0[1];
            h0p[p][0] = a0.x; h0p[p][1] = a0.y;
            h0p[p][2] = b0.x; h0p[p][3] = b0.y;
            const ulonglong2* r1 = (const ulonglong2*)&h1s[s][p][ql][0];
            ulonglong2 a1 = r1[0], b1 = r1[1];
            h1p[p][0] = a1.x; h1p[p][1] = a1.y;
            h1p[p][2] = b1.x; h1p[p][3] = b1.y;
        }
        xa = na; xb = nb; xp = xn;
    }

    // ============ Epilogue: h1(T-1) = L1(h0(T-1), h1(T-2)) + FC ============
    {
        float h1fin[4];
#pragma unroll
        for (int p = 0; p < 4; p++) {
            float z[4];
#pragma unroll
            for (int g = 0; g < 4; g++) {
                u64 acc = ffma2(wi1p[g][0], h0p[p][0], zb1p[g]);
#pragma unroll
                for (int m = 1; m < 4; m++)
                    acc = ffma2(wi1p[g][m], h0p[p][m], acc);
#pragma unroll
                for (int m = 0; m < 4; m++)
                    acc = ffma2(wh1p[g][m], h1p[p][m], acc);
                float2 u = unpack2(acc);
                z[g] = u.x + u.y;
            }
            float ig = fmaf(tanh_a(z[0]), 0.5f, 0.5f);
            float fg = fmaf(tanh_a(z[1]), 0.5f, 0.5f);
            float gg = tanh_a(z[2]);
            float og = fmaf(tanh_a(z[3]), 0.5f, 0.5f);
            c1[p] = fmaf(fg, c1[p], ig * gg);
            h1fin[p] = og * tanh_a(c1[p]);
        }

        // FC: out[b] = sum_j fc_w[j]*h1[j] + fc_b via width-8 shfl reduction.
        float fwj = __ldg(&fc_w[j]);
        float fb  = __ldg(&fc_b[0]);
        float4 o;
        float* op = &o.x;
#pragma unroll
        for (int p = 0; p < 4; p++) {
            float v = fwj * h1fin[p];
#pragma unroll
            for (int d = 4; d >= 1; d >>= 1)
                v += __shfl_down_sync(0xffffffffu, v, d, 8);
            op[p] = v + fb;
        }
        if (valid && j == 0)
            *(float4*)&out[4 * q] = o;
    }
}

extern "C" void kernel_launch(void* const* d_in, const int* in_sizes, int n_in,
                              void* d_out, int out_size)
{
    const float* x      = (const float*)d_in[0];
    const float* w_ih0  = (const float*)d_in[1];
    const float* w_hh0  = (const float*)d_in[2];
    const float* b_ih0  = (const float*)d_in[3];
    const float* b_hh0  = (const float*)d_in[4];
    const float* w_ih1  = (const float*)d_in[5];
    const float* w_hh1  = (const float*)d_in[6];
    const float* b_ih1  = (const float*)d_in[7];
    const float* b_hh1  = (const float*)d_in[8];
    const float* fc_w   = (const float*)d_in[9];
    const float* fc_b   = (const float*)d_in[10];
    float* out = (float*)d_out;

    int B = out_size;                 // [B, 1]
    int T = in_sizes[0] / (2 * B);    // x: [T, B, 2]

    int blocks = (B + 15) / 16;       // 16 elements per warp-block
    lstm2_fc_kernel<<<blocks, 32>>>(x, w_ih0, w_hh0, b_ih0, b_hh0,
                                    w_ih1, w_hh1, b_ih1, b_hh1,
                                    fc_w, fc_b, out, T, B);
}